// round 5
// baseline (speedup 1.0000x reference)
#include <cuda_runtime.h>
#include <math.h>
#include <stdint.h>

#define NN 50000
#define NE 800000
#define NG 64
#define NC 10
#define CHUNK 1024
#define NCHUNK ((NN + CHUNK - 1) / CHUNK)   // 49

// packed f32x2 fma: d = a*b + c elementwise on 2 packed floats
__device__ __forceinline__ unsigned long long ffma2(unsigned long long a,
                                                    unsigned long long b,
                                                    unsigned long long c) {
    unsigned long long d;
    asm("fma.rn.f32x2 %0, %1, %2, %3;" : "=l"(d) : "l"(a), "l"(b), "l"(c));
    return d;
}
__device__ __forceinline__ float lo32(unsigned long long v) {
    return __uint_as_float((unsigned)(v & 0xFFFFFFFFull));
}
__device__ __forceinline__ float hi32(unsigned long long v) {
    return __uint_as_float((unsigned)(v >> 32));
}

// ---------------- scratch (static device globals; no runtime alloc) --------
__device__ __align__(16) float g_dinv[NN];
__device__ int   g_cnt[NN];
__device__ int   g_rowptr[NN + 1];
__device__ int   g_cursor[NN];
__device__ int   g_col[NE];
__device__ float g_val[NE];
__device__ int   g_chunksum[NCHUNK];
__device__ int   g_chunkoff[NCHUNK];
__device__ __align__(16) float g_bufA[NN * 256];
__device__ __align__(16) float g_bufB[NN * 256];
__device__ __align__(16) float g_bufT[NN * 128];
__device__ float g_pool[NG * 256];
__device__ float g_gcnt[NG];

// ---------------- preprocessing kernels ------------------------------------
__global__ void zero_kernel() {
    int i = blockIdx.x * blockDim.x + threadIdx.x;
    if (i < NN) g_cnt[i] = 0;
    if (i < NG * 256) g_pool[i] = 0.f;
    if (i < NG) g_gcnt[i] = 0.f;
}

__global__ void count_kernel(const int* __restrict__ ei) {
    int e = blockIdx.x * blockDim.x + threadIdx.x;
    if (e < NE) atomicAdd(&g_cnt[ei[NE + e]], 1);
}

__global__ void chunkred_kernel() {
    int c = blockIdx.x, tid = threadIdx.x;
    int base = c * CHUNK;
    int s = 0;
    #pragma unroll
    for (int k = 0; k < CHUNK / 256; k++) {
        int idx = base + tid + k * 256;
        if (idx < NN) {
            int v = g_cnt[idx];
            s += v;
            g_dinv[idx] = rsqrtf((float)(v + 1));
        }
    }
    for (int off = 16; off; off >>= 1) s += __shfl_down_sync(~0u, s, off);
    __shared__ int sm[8];
    if ((tid & 31) == 0) sm[tid >> 5] = s;
    __syncthreads();
    if (tid < 8) {
        int t = sm[tid];
        for (int off = 4; off; off >>= 1) t += __shfl_down_sync(0xff, t, off);
        if (tid == 0) g_chunksum[c] = t;
    }
}

__global__ void chunkoff_kernel() {
    int tid = threadIdx.x;
    int lane = tid & 31, w = tid >> 5;
    int v = (tid < NCHUNK) ? g_chunksum[tid] : 0;
    int incl = v;
    for (int off = 1; off < 32; off <<= 1) {
        int t = __shfl_up_sync(~0u, incl, off);
        if (lane >= off) incl += t;
    }
    __shared__ int ws[2];
    if (lane == 31) ws[w] = incl;
    __syncthreads();
    int excl = incl - v + (w == 1 ? ws[0] : 0);
    if (tid < NCHUNK) g_chunkoff[tid] = excl;
}

__global__ void chunkscan_kernel() {
    __shared__ int warpsum[32];
    int c = blockIdx.x, tid = threadIdx.x;
    int i = c * CHUNK + tid;
    int v = (i < NN) ? g_cnt[i] : 0;
    int lane = tid & 31, w = tid >> 5;
    int incl = v;
    for (int off = 1; off < 32; off <<= 1) {
        int t = __shfl_up_sync(~0u, incl, off);
        if (lane >= off) incl += t;
    }
    if (lane == 31) warpsum[w] = incl;
    __syncthreads();
    if (w == 0) {
        int ws = warpsum[lane];
        for (int off = 1; off < 32; off <<= 1) {
            int t = __shfl_up_sync(~0u, ws, off);
            if (lane >= off) ws += t;
        }
        warpsum[lane] = ws;
    }
    __syncthreads();
    int excl = incl - v + (w > 0 ? warpsum[w - 1] : 0) + g_chunkoff[c];
    if (i < NN) { g_rowptr[i] = excl; g_cursor[i] = excl; }
    if (i == NN - 1) g_rowptr[NN] = excl + v;
}

__global__ void fill_kernel(const int* __restrict__ ei) {
    int e = blockIdx.x * blockDim.x + threadIdx.x;
    if (e >= NE) return;
    int s = ei[e];
    int d = ei[NE + e];
    int pos = atomicAdd(&g_cursor[d], 1);
    g_col[pos] = s;
    g_val[pos] = g_dinv[s] * g_dinv[d];
}

// ---------------- aggregation ------------------------------------------------
template <int F>
__global__ void agg_kernel(const float* __restrict__ h, float* __restrict__ out) {
    int node = blockIdx.x * blockDim.y + threadIdx.y;
    if (node >= NN) return;
    int f = threadIdx.x;
    float dv = g_dinv[node];
    float acc = dv * dv * __ldg(&h[node * F + f]);
    int e = g_rowptr[node], end = g_rowptr[node + 1];
    for (; e < end; e++) acc += g_val[e] * __ldg(&h[g_col[e] * F + f]);
    out[node * F + f] = acc;
}

template <int F>
__global__ void agg4_kernel(const float4* __restrict__ h, float4* __restrict__ out) {
    constexpr int FQ = F / 4;
    int node = blockIdx.x * blockDim.y + threadIdx.y;
    if (node >= NN) return;
    int f = threadIdx.x;
    float dv = g_dinv[node];
    float4 hv = __ldg(&h[node * FQ + f]);
    float s = dv * dv;
    float4 acc = make_float4(s * hv.x, s * hv.y, s * hv.z, s * hv.w);
    int e = g_rowptr[node], end = g_rowptr[node + 1];
    for (; e + 1 < end; e += 2) {
        float w0 = g_val[e], w1 = g_val[e + 1];
        float4 n0 = __ldg(&h[g_col[e] * FQ + f]);
        float4 n1 = __ldg(&h[g_col[e + 1] * FQ + f]);
        acc.x += w0 * n0.x + w1 * n1.x;
        acc.y += w0 * n0.y + w1 * n1.y;
        acc.z += w0 * n0.z + w1 * n1.z;
        acc.w += w0 * n0.w + w1 * n1.w;
    }
    if (e < end) {
        float w0 = g_val[e];
        float4 n0 = __ldg(&h[g_col[e] * FQ + f]);
        acc.x += w0 * n0.x; acc.y += w0 * n0.y;
        acc.z += w0 * n0.z; acc.w += w0 * n0.w;
    }
    out[node * FQ + f] = acc;
}

// ---------------- dense: out = relu(in @ W + b) ----------------------------
// 256 threads/block, 4 features x TN nodes per thread.
// K even: packed f32x2 path (weights staged as [K/2][F][2] pairs in SMEM).
template <int K, int F, int TN>
__global__ __launch_bounds__(256) void gemm_relu_kernel(
    const float* __restrict__ in, const float* __restrict__ W,
    const float* __restrict__ bias, float* __restrict__ out)
{
    constexpr int TF = 4;
    constexpr int BX = F / TF;
    constexpr int BY = 256 / BX;
    constexpr int NT = TN * BY;
    constexpr int NTILES = (NN + NT - 1) / NT;
    extern __shared__ float fsm[];
    float* sW = fsm;               // [K][F] (scalar path) or [K/2][F][2] (packed)
    float* sh = fsm + K * F;       // [NT][K]
    int tid = threadIdx.y * BX + threadIdx.x;
    int fq = threadIdx.x;

    if constexpr (K % 2 == 0) {
        // paired layout: sW[(k/2)*2F + f*2 + (k&1)]
        for (int i = tid; i < K * F; i += 256) {
            int k = i / F, f = i - k * F;
            sW[(k >> 1) * (2 * F) + f * 2 + (k & 1)] = W[i];
        }
    } else {
        const float* Ws = W;
        for (int i = tid; i < K * F; i += 256) sW[i] = Ws[i];
    }

    float4 bv = ((const float4*)bias)[fq];

    for (int tile = blockIdx.x; tile < NTILES; tile += gridDim.x) {
        int node0 = tile * NT;
        __syncthreads();   // protects sh reuse AND first-use of sW
        if constexpr (K % 4 == 0) {
            constexpr int KQ = K / 4;
            const float4* inv4 = (const float4*)in;
            float4* shv = (float4*)sh;
            for (int i = tid; i < NT * KQ; i += 256) {
                int j = i / KQ;
                int nd = node0 + j;
                shv[i] = (nd < NN) ? inv4[nd * KQ + (i - j * KQ)]
                                   : make_float4(0.f, 0.f, 0.f, 0.f);
            }
        } else {
            for (int i = tid; i < NT * K; i += 256) {
                int j = i / K, k = i - j * K;
                int nd = node0 + j;
                sh[i] = (nd < NN) ? in[nd * K + k] : 0.f;
            }
        }
        __syncthreads();

        if constexpr (K % 2 == 0) {
            // -------- packed f32x2 path --------
            unsigned long long acc2[TN][4];
            #pragma unroll
            for (int j = 0; j < TN; j++)
                #pragma unroll
                for (int q = 0; q < 4; q++) acc2[j][q] = 0ull;

            const float* shb = sh + threadIdx.y * TN * K;
            #pragma unroll 4
            for (int kk = 0; kk < K / 2; kk++) {
                const ulonglong2* wrow = (const ulonglong2*)(sW + kk * (2 * F));
                ulonglong2 wlo = wrow[2 * fq];       // pairs for features 4fq, 4fq+1
                ulonglong2 whi = wrow[2 * fq + 1];   // pairs for features 4fq+2, 4fq+3
                #pragma unroll
                for (int j = 0; j < TN; j++) {
                    unsigned long long hp =
                        *(const unsigned long long*)(shb + j * K + 2 * kk);
                    acc2[j][0] = ffma2(hp, wlo.x, acc2[j][0]);
                    acc2[j][1] = ffma2(hp, wlo.y, acc2[j][1]);
                    acc2[j][2] = ffma2(hp, whi.x, acc2[j][2]);
                    acc2[j][3] = ffma2(hp, whi.y, acc2[j][3]);
                }
            }
            #pragma unroll
            for (int j = 0; j < TN; j++) {
                int node = node0 + threadIdx.y * TN + j;
                if (node < NN) {
                    float4 o;
                    o.x = fmaxf(lo32(acc2[j][0]) + hi32(acc2[j][0]) + bv.x, 0.f);
                    o.y = fmaxf(lo32(acc2[j][1]) + hi32(acc2[j][1]) + bv.y, 0.f);
                    o.z = fmaxf(lo32(acc2[j][2]) + hi32(acc2[j][2]) + bv.z, 0.f);
                    o.w = fmaxf(lo32(acc2[j][3]) + hi32(acc2[j][3]) + bv.w, 0.f);
                    ((float4*)out)[node * BX + fq] = o;
                }
            }
        } else {
            // -------- scalar path (K odd, layer 1) --------
            float acc[TN][4];
            #pragma unroll
            for (int j = 0; j < TN; j++) {
                acc[j][0] = bv.x; acc[j][1] = bv.y; acc[j][2] = bv.z; acc[j][3] = bv.w;
            }
            const float* shb = sh + threadIdx.y * TN * K;
            #pragma unroll
            for (int k = 0; k < K; k++) {
                float4 w = ((const float4*)sW)[k * BX + fq];
                #pragma unroll
                for (int j = 0; j < TN; j++) {
                    float hv = shb[j * K + k];
                    acc[j][0] += w.x * hv;
                    acc[j][1] += w.y * hv;
                    acc[j][2] += w.z * hv;
                    acc[j][3] += w.w * hv;
                }
            }
            #pragma unroll
            for (int j = 0; j < TN; j++) {
                int node = node0 + threadIdx.y * TN + j;
                if (node < NN) {
                    float4 o;
                    o.x = fmaxf(acc[j][0], 0.f);
                    o.y = fmaxf(acc[j][1], 0.f);
                    o.z = fmaxf(acc[j][2], 0.f);
                    o.w = fmaxf(acc[j][3], 0.f);
                    ((float4*)out)[node * BX + fq] = o;
                }
            }
        }
    }
}

// ---------------- mean-pool pieces -----------------------------------------
__global__ void pool_kernel(const float* __restrict__ h, const int* __restrict__ batch) {
    const int CH = 64;
    int f = threadIdx.x;
    int n0 = blockIdx.x * CH;
    float acc = 0.f;
    int curg = -1;
    for (int i = 0; i < CH; i++) {
        int nd = n0 + i;
        if (nd >= NN) break;
        int g = batch[nd];
        if (g != curg) {
            if (curg >= 0) atomicAdd(&g_pool[curg * 256 + f], acc);
            acc = 0.f; curg = g;
        }
        acc += h[nd * 256 + f];
    }
    if (curg >= 0) atomicAdd(&g_pool[curg * 256 + f], acc);
}

__global__ void gcnt_kernel(const int* __restrict__ batch) {
    int i = blockIdx.x * blockDim.x + threadIdx.x;
    if (i < NN) atomicAdd(&g_gcnt[batch[i]], 1.f);
}

__global__ void head_kernel(const float* __restrict__ fcW, const float* __restrict__ fcb,
                            float* __restrict__ out) {
    __shared__ float slog[NG * NC];
    int tid = threadIdx.x;
    if (tid < NG * NC) {
        int g = tid / NC, c = tid % NC;
        float inv = 1.f / fmaxf(g_gcnt[g], 1.f);
        float a = fcb[c];
        for (int k = 0; k < 256; k++)
            a += g_pool[g * 256 + k] * inv * fcW[k * NC + c];
        slog[tid] = a;
    }
    __syncthreads();
    if (tid < NG * NC) {
        int g = tid / NC;
        float m = -1e30f;
        for (int i = 0; i < NC; i++) m = fmaxf(m, slog[g * NC + i]);
        float s = 0.f;
        for (int i = 0; i < NC; i++) s += expf(slog[g * NC + i] - m);
        out[tid] = slog[tid] - m - logf(s);
    }
}

// ---------------- launch -----------------------------------------------------
extern "C" void kernel_launch(void* const* d_in, const int* in_sizes, int n_in,
                              void* d_out, int out_size) {
    const float* x   = (const float*)d_in[0];
    const int*   ei  = (const int*)d_in[1];
    const int*   bat = (const int*)d_in[2];
    const float* W1 = (const float*)d_in[3];
    const float* b1 = (const float*)d_in[4];
    const float* W2 = (const float*)d_in[5];
    const float* b2 = (const float*)d_in[6];
    const float* W3 = (const float*)d_in[7];
    const float* b3 = (const float*)d_in[8];
    const float* W4 = (const float*)d_in[9];
    const float* b4 = (const float*)d_in[10];
    const float* fcW = (const float*)d_in[11];
    const float* fcb = (const float*)d_in[12];
    float* out = (float*)d_out;

    float *bufA, *bufB, *bufT;
    cudaGetSymbolAddress((void**)&bufA, g_bufA);
    cudaGetSymbolAddress((void**)&bufB, g_bufB);
    cudaGetSymbolAddress((void**)&bufT, g_bufT);

    cudaFuncSetAttribute(gemm_relu_kernel<128, 256, 8>,
                         cudaFuncAttributeMaxDynamicSharedMemorySize,
                         (128 * 256 + 32 * 128) * 4);
    cudaFuncSetAttribute(gemm_relu_kernel<64, 128, 8>,
                         cudaFuncAttributeMaxDynamicSharedMemorySize,
                         (64 * 128 + 64 * 64) * 4);

    const int EB = (NE + 255) / 256;
    const int NB = (NN + 255) / 256;

    zero_kernel<<<NB, 256>>>();
    count_kernel<<<EB, 256>>>(ei);
    chunkred_kernel<<<NCHUNK, 256>>>();
    chunkoff_kernel<<<1, 64>>>();
    chunkscan_kernel<<<NCHUNK, 1024>>>();
    fill_kernel<<<EB, 256>>>(ei);

    // layer 1: agg(x)[5] -> @W1 -> relu -> bufA[32]
    {
        dim3 blk(5, 51);
        agg_kernel<5><<<(NN + 50) / 51, blk>>>(x, bufT);
        int smem = (5 * 32 + 128 * 5) * 4;
        gemm_relu_kernel<5, 32, 4><<<391, dim3(8, 32), smem>>>(bufT, W1, b1, bufA);
    }
    // layer 2: agg(bufA)[32] -> @W2 -> relu -> bufB[64]
    {
        dim3 blk(8, 32);
        agg4_kernel<32><<<(NN + 31) / 32, blk>>>((const float4*)bufA, (float4*)bufT);
        int smem = (32 * 64 + 64 * 32) * 4;
        gemm_relu_kernel<32, 64, 4><<<592, dim3(16, 16), smem>>>(bufT, W2, b2, bufB);
    }
    // layer 3: agg(bufB)[64] -> @W3 -> relu -> bufA[128]
    {
        dim3 blk(16, 16);
        agg4_kernel<64><<<(NN + 15) / 16, blk>>>((const float4*)bufB, (float4*)bufT);
        int smem = (64 * 128 + 64 * 64) * 4;
        gemm_relu_kernel<64, 128, 8><<<592, dim3(32, 8), smem>>>(bufT, W3, b3, bufA);
    }
    // layer 4: agg(bufA)[128] -> @W4 -> relu -> bufB[256]
    {
        dim3 blk(32, 8);
        agg4_kernel<128><<<(NN + 7) / 8, blk>>>((const float4*)bufA, (float4*)bufT);
        int smem = (128 * 256 + 32 * 128) * 4;
        gemm_relu_kernel<128, 256, 8><<<148, dim3(64, 4), smem>>>(bufT, W4, b4, bufB);
    }

    // mean pool + head
    pool_kernel<<<(NN + 63) / 64, 256>>>(bufB, bat);
    gcnt_kernel<<<NB, 256>>>(bat);
    head_kernel<<<1, 640>>>(fcW, fcb, out);

    (void)in_sizes; (void)n_in; (void)out_size;
}

// round 6
// speedup vs baseline: 1.1499x; 1.1499x over previous
#include <cuda_runtime.h>
#include <math.h>
#include <stdint.h>

#define NN 50000
#define NE 800000
#define NG 64
#define NC 10
#define CHUNK 1024
#define NCHUNK ((NN + CHUNK - 1) / CHUNK)   // 49

__device__ __forceinline__ uint32_t f2tf32(float x) {
    uint32_t u;
    asm("cvt.rna.tf32.f32 %0, %1;" : "=r"(u) : "f"(x));
    return u;
}

// ---------------- scratch (static device globals; no runtime alloc) --------
__device__ __align__(16) float g_dinv[NN];
__device__ int   g_cnt[NN];
__device__ int   g_rowptr[NN + 1];
__device__ int   g_cursor[NN];
__device__ int   g_col[NE];
__device__ float g_val[NE];
__device__ int   g_chunksum[NCHUNK];
__device__ int   g_chunkoff[NCHUNK];
__device__ __align__(16) float g_bufA[NN * 256];
__device__ __align__(16) float g_bufB[NN * 256];
__device__ __align__(16) float g_bufT[NN * 128];
__device__ __align__(16) float g_Wt3[128 * 64];    // W3^T, tf32-rounded
__device__ __align__(16) float g_Wt4[256 * 128];   // W4^T, tf32-rounded
__device__ float g_pool[NG * 256];
__device__ float g_gcnt[NG];

// ---------------- preprocessing kernels ------------------------------------
__global__ void zero_kernel() {
    int i = blockIdx.x * blockDim.x + threadIdx.x;
    if (i < NN) g_cnt[i] = 0;
    if (i < NG * 256) g_pool[i] = 0.f;
    if (i < NG) g_gcnt[i] = 0.f;
}

__global__ void count_kernel(const int* __restrict__ ei) {
    int e = blockIdx.x * blockDim.x + threadIdx.x;
    if (e < NE) atomicAdd(&g_cnt[ei[NE + e]], 1);
}

// transpose + tf32-round weights for the mma layers
__global__ void convw_kernel(const float* __restrict__ W3, const float* __restrict__ W4) {
    int i = blockIdx.x * blockDim.x + threadIdx.x;
    if (i < 128 * 64) {
        int n = i >> 6, k = i & 63;
        g_Wt3[i] = __uint_as_float(f2tf32(W3[k * 128 + n]));
    }
    if (i < 256 * 128) {
        int n = i >> 7, k = i & 127;
        g_Wt4[i] = __uint_as_float(f2tf32(W4[k * 256 + n]));
    }
}

__global__ void chunkred_kernel() {
    int c = blockIdx.x, tid = threadIdx.x;
    int base = c * CHUNK;
    int s = 0;
    #pragma unroll
    for (int k = 0; k < CHUNK / 256; k++) {
        int idx = base + tid + k * 256;
        if (idx < NN) {
            int v = g_cnt[idx];
            s += v;
            g_dinv[idx] = rsqrtf((float)(v + 1));
        }
    }
    for (int off = 16; off; off >>= 1) s += __shfl_down_sync(~0u, s, off);
    __shared__ int sm[8];
    if ((tid & 31) == 0) sm[tid >> 5] = s;
    __syncthreads();
    if (tid < 8) {
        int t = sm[tid];
        for (int off = 4; off; off >>= 1) t += __shfl_down_sync(0xff, t, off);
        if (tid == 0) g_chunksum[c] = t;
    }
}

__global__ void chunkoff_kernel() {
    int tid = threadIdx.x;
    int lane = tid & 31, w = tid >> 5;
    int v = (tid < NCHUNK) ? g_chunksum[tid] : 0;
    int incl = v;
    for (int off = 1; off < 32; off <<= 1) {
        int t = __shfl_up_sync(~0u, incl, off);
        if (lane >= off) incl += t;
    }
    __shared__ int ws[2];
    if (lane == 31) ws[w] = incl;
    __syncthreads();
    int excl = incl - v + (w == 1 ? ws[0] : 0);
    if (tid < NCHUNK) g_chunkoff[tid] = excl;
}

__global__ void chunkscan_kernel() {
    __shared__ int warpsum[32];
    int c = blockIdx.x, tid = threadIdx.x;
    int i = c * CHUNK + tid;
    int v = (i < NN) ? g_cnt[i] : 0;
    int lane = tid & 31, w = tid >> 5;
    int incl = v;
    for (int off = 1; off < 32; off <<= 1) {
        int t = __shfl_up_sync(~0u, incl, off);
        if (lane >= off) incl += t;
    }
    if (lane == 31) warpsum[w] = incl;
    __syncthreads();
    if (w == 0) {
        int ws = warpsum[lane];
        for (int off = 1; off < 32; off <<= 1) {
            int t = __shfl_up_sync(~0u, ws, off);
            if (lane >= off) ws += t;
        }
        warpsum[lane] = ws;
    }
    __syncthreads();
    int excl = incl - v + (w > 0 ? warpsum[w - 1] : 0) + g_chunkoff[c];
    if (i < NN) { g_rowptr[i] = excl; g_cursor[i] = excl; }
    if (i == NN - 1) g_rowptr[NN] = excl + v;
}

__global__ void fill_kernel(const int* __restrict__ ei) {
    int e = blockIdx.x * blockDim.x + threadIdx.x;
    if (e >= NE) return;
    int s = ei[e];
    int d = ei[NE + e];
    int pos = atomicAdd(&g_cursor[d], 1);
    g_col[pos] = s;
    g_val[pos] = g_dinv[s] * g_dinv[d];
}

// ---------------- aggregation ------------------------------------------------
template <int F>
__global__ void agg_kernel(const float* __restrict__ h, float* __restrict__ out) {
    int node = blockIdx.x * blockDim.y + threadIdx.y;
    if (node >= NN) return;
    int f = threadIdx.x;
    float dv = g_dinv[node];
    float acc = dv * dv * __ldg(&h[node * F + f]);
    int e = g_rowptr[node], end = g_rowptr[node + 1];
    for (; e < end; e++) acc += g_val[e] * __ldg(&h[g_col[e] * F + f]);
    out[node * F + f] = acc;
}

template <int F>
__global__ void agg4_kernel(const float4* __restrict__ h, float4* __restrict__ out) {
    constexpr int FQ = F / 4;
    int node = blockIdx.x * blockDim.y + threadIdx.y;
    if (node >= NN) return;
    int f = threadIdx.x;
    float dv = g_dinv[node];
    float4 hv = __ldg(&h[node * FQ + f]);
    float s = dv * dv;
    float4 acc = make_float4(s * hv.x, s * hv.y, s * hv.z, s * hv.w);
    int e = g_rowptr[node], end = g_rowptr[node + 1];
    for (; e + 1 < end; e += 2) {
        float w0 = g_val[e], w1 = g_val[e + 1];
        float4 n0 = __ldg(&h[g_col[e] * FQ + f]);
        float4 n1 = __ldg(&h[g_col[e + 1] * FQ + f]);
        acc.x += w0 * n0.x + w1 * n1.x;
        acc.y += w0 * n0.y + w1 * n1.y;
        acc.z += w0 * n0.z + w1 * n1.z;
        acc.w += w0 * n0.w + w1 * n1.w;
    }
    if (e < end) {
        float w0 = g_val[e];
        float4 n0 = __ldg(&h[g_col[e] * FQ + f]);
        acc.x += w0 * n0.x; acc.y += w0 * n0.y;
        acc.z += w0 * n0.z; acc.w += w0 * n0.w;
    }
    out[node * FQ + f] = acc;
}

// ---------------- tf32 tensor-core GEMM: out = relu(in @ W + b) -------------
// in: [NN][K] f32, Wt: [NTOT][K] tf32-rounded f32, out: [NN][NTOT].
// CTA: 256 thr, 128-node tile x 128-col slice (blockIdx.y). 8 warps x 16 rows.
template <int K, int NTOT>
__global__ __launch_bounds__(256) void mma_tf32_kernel(
    const float* __restrict__ in, const float* __restrict__ Wt,
    const float* __restrict__ bias, float* __restrict__ out)
{
    constexpr int AS = K + 4;     // padded row stride (floats), conflict-free
    constexpr int NS = 128;       // cols per CTA
    constexpr int KQ = K / 4;
    extern __shared__ float smem[];
    float* sA = smem;             // [128][AS]
    float* sB = smem + 128 * AS;  // [NS][AS]
    int tid = threadIdx.x;
    int node0 = blockIdx.x * 128;
    int n0 = blockIdx.y * NS;

    // stage A (round to tf32) and B (already tf32 bits)
    for (int i = tid; i < 128 * KQ; i += 256) {
        int r = i / KQ, kq = i - r * KQ;
        int nd = node0 + r;
        float4 v = make_float4(0.f, 0.f, 0.f, 0.f);
        if (nd < NN) v = __ldg((const float4*)in + (size_t)nd * KQ + kq);
        float* dst = sA + r * AS + kq * 4;
        dst[0] = __uint_as_float(f2tf32(v.x));
        dst[1] = __uint_as_float(f2tf32(v.y));
        dst[2] = __uint_as_float(f2tf32(v.z));
        dst[3] = __uint_as_float(f2tf32(v.w));
    }
    for (int i = tid; i < NS * KQ; i += 256) {
        int r = i / KQ, kq = i - r * KQ;
        float4 v = __ldg((const float4*)Wt + (size_t)(n0 + r) * KQ + kq);
        *(float4*)(sB + r * AS + kq * 4) = v;
    }
    __syncthreads();

    int warp = tid >> 5, lane = tid & 31;
    int g = lane >> 2, tg = lane & 3;
    int mrow = warp * 16;

    // A fragments, register-resident over all K
    uint32_t a[K / 8][4];
    #pragma unroll
    for (int kk = 0; kk < K / 8; kk++) {
        const float* p0 = sA + (mrow + g) * AS + kk * 8 + tg;
        const float* p1 = sA + (mrow + g + 8) * AS + kk * 8 + tg;
        a[kk][0] = __float_as_uint(p0[0]);
        a[kk][1] = __float_as_uint(p1[0]);
        a[kk][2] = __float_as_uint(p0[4]);
        a[kk][3] = __float_as_uint(p1[4]);
    }

    int row0 = node0 + mrow + g;
    int row1 = row0 + 8;
    #pragma unroll 2
    for (int ng = 0; ng < NS / 8; ng++) {
        float d0 = 0.f, d1 = 0.f, d2 = 0.f, d3 = 0.f;
        const float* bp = sB + (ng * 8 + g) * AS + tg;
        #pragma unroll
        for (int kk = 0; kk < K / 8; kk++) {
            uint32_t b0 = __float_as_uint(bp[kk * 8]);
            uint32_t b1 = __float_as_uint(bp[kk * 8 + 4]);
            asm volatile(
                "mma.sync.aligned.m16n8k8.row.col.f32.tf32.tf32.f32 "
                "{%0,%1,%2,%3}, {%4,%5,%6,%7}, {%8,%9}, {%0,%1,%2,%3};"
                : "+f"(d0), "+f"(d1), "+f"(d2), "+f"(d3)
                : "r"(a[kk][0]), "r"(a[kk][1]), "r"(a[kk][2]), "r"(a[kk][3]),
                  "r"(b0), "r"(b1));
        }
        int col = n0 + ng * 8 + 2 * tg;
        float2 bs = __ldg((const float2*)&bias[col]);
        if (row0 < NN) {
            float2 o;
            o.x = fmaxf(d0 + bs.x, 0.f);
            o.y = fmaxf(d1 + bs.y, 0.f);
            *(float2*)(out + (size_t)row0 * NTOT + col) = o;
        }
        if (row1 < NN) {
            float2 o;
            o.x = fmaxf(d2 + bs.x, 0.f);
            o.y = fmaxf(d3 + bs.y, 0.f);
            *(float2*)(out + (size_t)row1 * NTOT + col) = o;
        }
    }
}

// ---------------- dense FFMA (layers 1-2): out = relu(in @ W + b) -----------
template <int K, int F, int TN>
__global__ __launch_bounds__(256) void gemm_relu_kernel(
    const float* __restrict__ in, const float* __restrict__ W,
    const float* __restrict__ bias, float* __restrict__ out)
{
    constexpr int TF = 4;
    constexpr int BX = F / TF;
    constexpr int BY = 256 / BX;
    constexpr int NT = TN * BY;
    constexpr int NTILES = (NN + NT - 1) / NT;
    extern __shared__ float fsm[];
    float* sW = fsm;
    float* sh = fsm + K * F;
    int tid = threadIdx.y * BX + threadIdx.x;

    const float4* Wv = (const float4*)W;
    float4* sWv = (float4*)sW;
    for (int i = tid; i < K * F / 4; i += 256) sWv[i] = Wv[i];

    int fq = threadIdx.x;
    float4 bv = ((const float4*)bias)[fq];

    for (int tile = blockIdx.x; tile < NTILES; tile += gridDim.x) {
        int node0 = tile * NT;
        __syncthreads();
        if constexpr (K % 4 == 0) {
            constexpr int KQ = K / 4;
            const float4* inv4 = (const float4*)in;
            float4* shv = (float4*)sh;
            for (int i = tid; i < NT * KQ; i += 256) {
                int j = i / KQ;
                int nd = node0 + j;
                shv[i] = (nd < NN) ? inv4[nd * KQ + (i - j * KQ)]
                                   : make_float4(0.f, 0.f, 0.f, 0.f);
            }
        } else {
            for (int i = tid; i < NT * K; i += 256) {
                int j = i / K, k = i - j * K;
                int nd = node0 + j;
                sh[i] = (nd < NN) ? in[nd * K + k] : 0.f;
            }
        }
        __syncthreads();

        float acc[TN][4];
        #pragma unroll
        for (int j = 0; j < TN; j++) {
            acc[j][0] = bv.x; acc[j][1] = bv.y; acc[j][2] = bv.z; acc[j][3] = bv.w;
        }
        const float* shb = sh + threadIdx.y * TN * K;
        #pragma unroll 4
        for (int k = 0; k < K; k++) {
            float4 w = ((const float4*)sW)[k * BX + fq];
            #pragma unroll
            for (int j = 0; j < TN; j++) {
                float hv = shb[j * K + k];
                acc[j][0] += w.x * hv;
                acc[j][1] += w.y * hv;
                acc[j][2] += w.z * hv;
                acc[j][3] += w.w * hv;
            }
        }
        #pragma unroll
        for (int j = 0; j < TN; j++) {
            int node = node0 + threadIdx.y * TN + j;
            if (node < NN) {
                float4 o;
                o.x = fmaxf(acc[j][0], 0.f);
                o.y = fmaxf(acc[j][1], 0.f);
                o.z = fmaxf(acc[j][2], 0.f);
                o.w = fmaxf(acc[j][3], 0.f);
                ((float4*)out)[node * BX + fq] = o;
            }
        }
    }
}

// ---------------- mean-pool pieces -----------------------------------------
__global__ void pool_kernel(const float* __restrict__ h, const int* __restrict__ batch) {
    const int CH = 64;
    int f = threadIdx.x;
    int n0 = blockIdx.x * CH;
    float acc = 0.f;
    int curg = -1;
    for (int i = 0; i < CH; i++) {
        int nd = n0 + i;
        if (nd >= NN) break;
        int g = batch[nd];
        if (g != curg) {
            if (curg >= 0) atomicAdd(&g_pool[curg * 256 + f], acc);
            acc = 0.f; curg = g;
        }
        acc += h[nd * 256 + f];
    }
    if (curg >= 0) atomicAdd(&g_pool[curg * 256 + f], acc);
}

__global__ void gcnt_kernel(const int* __restrict__ batch) {
    int i = blockIdx.x * blockDim.x + threadIdx.x;
    if (i < NN) atomicAdd(&g_gcnt[batch[i]], 1.f);
}

__global__ void head_kernel(const float* __restrict__ fcW, const float* __restrict__ fcb,
                            float* __restrict__ out) {
    __shared__ float slog[NG * NC];
    int tid = threadIdx.x;
    if (tid < NG * NC) {
        int g = tid / NC, c = tid % NC;
        float inv = 1.f / fmaxf(g_gcnt[g], 1.f);
        float a = fcb[c];
        for (int k = 0; k < 256; k++)
            a += g_pool[g * 256 + k] * inv * fcW[k * NC + c];
        slog[tid] = a;
    }
    __syncthreads();
    if (tid < NG * NC) {
        int g = tid / NC;
        float m = -1e30f;
        for (int i = 0; i < NC; i++) m = fmaxf(m, slog[g * NC + i]);
        float s = 0.f;
        for (int i = 0; i < NC; i++) s += expf(slog[g * NC + i] - m);
        out[tid] = slog[tid] - m - logf(s);
    }
}

// ---------------- launch -----------------------------------------------------
extern "C" void kernel_launch(void* const* d_in, const int* in_sizes, int n_in,
                              void* d_out, int out_size) {
    const float* x   = (const float*)d_in[0];
    const int*   ei  = (const int*)d_in[1];
    const int*   bat = (const int*)d_in[2];
    const float* W1 = (const float*)d_in[3];
    const float* b1 = (const float*)d_in[4];
    const float* W2 = (const float*)d_in[5];
    const float* b2 = (const float*)d_in[6];
    const float* W3 = (const float*)d_in[7];
    const float* b3 = (const float*)d_in[8];
    const float* W4 = (const float*)d_in[9];
    const float* b4 = (const float*)d_in[10];
    const float* fcW = (const float*)d_in[11];
    const float* fcb = (const float*)d_in[12];
    float* out = (float*)d_out;

    float *bufA, *bufB, *bufT, *Wt3, *Wt4;
    cudaGetSymbolAddress((void**)&bufA, g_bufA);
    cudaGetSymbolAddress((void**)&bufB, g_bufB);
    cudaGetSymbolAddress((void**)&bufT, g_bufT);
    cudaGetSymbolAddress((void**)&Wt3, g_Wt3);
    cudaGetSymbolAddress((void**)&Wt4, g_Wt4);

    const int smL3 = (128 * (64 + 4) + 128 * (64 + 4)) * 4;     // 69632
    const int smL4 = (128 * (128 + 4) + 128 * (128 + 4)) * 4;   // 135168
    cudaFuncSetAttribute(mma_tf32_kernel<64, 128>,
                         cudaFuncAttributeMaxDynamicSharedMemorySize, smL3);
    cudaFuncSetAttribute(mma_tf32_kernel<128, 256>,
                         cudaFuncAttributeMaxDynamicSharedMemorySize, smL4);

    const int EB = (NE + 255) / 256;
    const int NB = (NN + 255) / 256;

    zero_kernel<<<NB, 256>>>();
    convw_kernel<<<128, 256>>>(W3, W4);
    count_kernel<<<EB, 256>>>(ei);
    chunkred_kernel<<<NCHUNK, 256>>>();
    chunkoff_kernel<<<1, 64>>>();
    chunkscan_kernel<<<NCHUNK, 1024>>>();
    fill_kernel<<<EB, 256>>>(ei);

    // layer 1: agg(x)[5] -> @W1 -> relu -> bufA[32]
    {
        dim3 blk(5, 51);
        agg_kernel<5><<<(NN + 50) / 51, blk>>>(x, bufT);
        int smem = (5 * 32 + 128 * 5) * 4;
        gemm_relu_kernel<5, 32, 4><<<391, dim3(8, 32), smem>>>(bufT, W1, b1, bufA);
    }
    // layer 2: agg(bufA)[32] -> @W2 -> relu -> bufB[64]
    {
        dim3 blk(8, 32);
        agg4_kernel<32><<<(NN + 31) / 32, blk>>>((const float4*)bufA, (float4*)bufT);
        int smem = (32 * 64 + 64 * 32) * 4;
        gemm_relu_kernel<32, 64, 4><<<592, dim3(16, 16), smem>>>(bufT, W2, b2, bufB);
    }
    // layer 3: agg(bufB)[64] -> tf32 mma -> bufA[128]
    {
        dim3 blk(16, 16);
        agg4_kernel<64><<<(NN + 15) / 16, blk>>>((const float4*)bufB, (float4*)bufT);
        mma_tf32_kernel<64, 128><<<dim3(391, 1), 256, smL3>>>(bufT, Wt3, b3, bufA);
    }
    // layer 4: agg(bufA)[128] -> tf32 mma -> bufB[256]
    {
        dim3 blk(32, 8);
        agg4_kernel<128><<<(NN + 7) / 8, blk>>>((const float4*)bufA, (float4*)bufT);
        mma_tf32_kernel<128, 256><<<dim3(391, 2), 256, smL4>>>(bufT, Wt4, b4, bufB);
    }

    // mean pool + head
    pool_kernel<<<(NN + 63) / 64, 256>>>(bufB, bat);
    gcnt_kernel<<<NB, 256>>>(bat);
    head_kernel<<<1, 640>>>(fcW, fcb, out);

    (void)in_sizes; (void)n_in; (void)out_size;
}

// round 7
// speedup vs baseline: 1.1681x; 1.0158x over previous
#include <cuda_runtime.h>
#include <math.h>
#include <stdint.h>

#define NN 50000
#define NE 800000
#define NG 64
#define NC 10
#define CHUNK 1024
#define NCHUNK ((NN + CHUNK - 1) / CHUNK)   // 49

__device__ __forceinline__ uint32_t f2tf32(float x) {
    uint32_t u;
    asm("cvt.rna.tf32.f32 %0, %1;" : "=r"(u) : "f"(x));
    return u;
}

// ---------------- scratch (static device globals; no runtime alloc) --------
__device__ __align__(16) float g_dinv[NN];
__device__ int   g_cnt[NN];
__device__ int   g_rowptr[NN + 1];
__device__ int   g_cursor[NN];
__device__ int   g_col[NE];
__device__ float g_val[NE];
__device__ int   g_chunksum[NCHUNK];
__device__ __align__(16) float g_bufA[NN * 256];
__device__ __align__(16) float g_bufB[NN * 256];
__device__ __align__(16) float g_bufT[NN * 128];
__device__ __align__(16) float g_Wt3[128 * 64];    // W3^T, tf32-rounded
__device__ __align__(16) float g_Wt4[256 * 128];   // W4^T, tf32-rounded
__device__ float g_pool[NG * 256];
__device__ float g_gcnt[NG];

// ---------------- init: zero + weight transpose/round -----------------------
__global__ void init_kernel(const float* __restrict__ W3, const float* __restrict__ W4) {
    int i = blockIdx.x * blockDim.x + threadIdx.x;
    if (i < NN) g_cnt[i] = 0;
    if (i < NG * 256) g_pool[i] = 0.f;
    if (i < NG) g_gcnt[i] = 0.f;
    if (i < 128 * 64) {
        int n = i >> 6, k = i & 63;
        g_Wt3[i] = __uint_as_float(f2tf32(W3[k * 128 + n]));
    }
    if (i < 256 * 128) {
        int n = i >> 7, k = i & 127;
        g_Wt4[i] = __uint_as_float(f2tf32(W4[k * 256 + n]));
    }
}

__global__ void count_kernel(const int* __restrict__ ei) {
    int e = blockIdx.x * blockDim.x + threadIdx.x;
    if (e < NE) atomicAdd(&g_cnt[ei[NE + e]], 1);
}

__global__ void chunkred_kernel() {
    int c = blockIdx.x, tid = threadIdx.x;
    int base = c * CHUNK;
    int s = 0;
    #pragma unroll
    for (int k = 0; k < CHUNK / 256; k++) {
        int idx = base + tid + k * 256;
        if (idx < NN) {
            int v = g_cnt[idx];
            s += v;
            g_dinv[idx] = rsqrtf((float)(v + 1));
        }
    }
    for (int off = 16; off; off >>= 1) s += __shfl_down_sync(~0u, s, off);
    __shared__ int sm[8];
    if ((tid & 31) == 0) sm[tid >> 5] = s;
    __syncthreads();
    if (tid < 8) {
        int t = sm[tid];
        for (int off = 4; off; off >>= 1) t += __shfl_down_sync(0xff, t, off);
        if (tid == 0) g_chunksum[c] = t;
    }
}

// per-chunk scan; each block derives its own base from the 49 chunk sums
__global__ void scan2_kernel() {
    __shared__ int warpsum[32];
    __shared__ int part[2];
    __shared__ int base_s;
    int c = blockIdx.x, tid = threadIdx.x;

    if (tid < 64) {
        int v = (tid < c && tid < NCHUNK) ? g_chunksum[tid] : 0;
        for (int off = 16; off; off >>= 1) v += __shfl_down_sync(~0u, v, off);
        if ((tid & 31) == 0) part[tid >> 5] = v;
    }
    __syncthreads();
    if (tid == 0) base_s = part[0] + part[1];
    __syncthreads();

    int i = c * CHUNK + tid;
    int v = (i < NN) ? g_cnt[i] : 0;
    int lane = tid & 31, w = tid >> 5;
    int incl = v;
    for (int off = 1; off < 32; off <<= 1) {
        int t = __shfl_up_sync(~0u, incl, off);
        if (lane >= off) incl += t;
    }
    if (lane == 31) warpsum[w] = incl;
    __syncthreads();
    if (w == 0) {
        int ws = warpsum[lane];
        for (int off = 1; off < 32; off <<= 1) {
            int t = __shfl_up_sync(~0u, ws, off);
            if (lane >= off) ws += t;
        }
        warpsum[lane] = ws;
    }
    __syncthreads();
    int excl = incl - v + (w > 0 ? warpsum[w - 1] : 0) + base_s;
    if (i < NN) { g_rowptr[i] = excl; g_cursor[i] = excl; }
    if (i == NN - 1) g_rowptr[NN] = excl + v;
}

// fill CSR + graph-size counts (independent work, fused)
__global__ void fillg_kernel(const int* __restrict__ ei, const int* __restrict__ bat) {
    int e = blockIdx.x * blockDim.x + threadIdx.x;
    if (e < NE) {
        int s = ei[e];
        int d = ei[NE + e];
        int pos = atomicAdd(&g_cursor[d], 1);
        g_col[pos] = s;
        g_val[pos] = g_dinv[s] * g_dinv[d];
    }
    if (e < NN) atomicAdd(&g_gcnt[bat[e]], 1.f);
}

// ---------------- aggregation ------------------------------------------------
template <int F>
__global__ void agg_kernel(const float* __restrict__ h, float* __restrict__ out) {
    int node = blockIdx.x * blockDim.y + threadIdx.y;
    if (node >= NN) return;
    int f = threadIdx.x;
    float dv = g_dinv[node];
    float acc = dv * dv * __ldg(&h[node * F + f]);
    int e = g_rowptr[node], end = g_rowptr[node + 1];
    for (; e < end; e++) acc += g_val[e] * __ldg(&h[g_col[e] * F + f]);
    out[node * F + f] = acc;
}

// float4 gather, 4-wide unrolled edge loop (MLP=4)
template <int F>
__global__ void agg4_kernel(const float4* __restrict__ h, float4* __restrict__ out) {
    constexpr int FQ = F / 4;
    int node = blockIdx.x * blockDim.y + threadIdx.y;
    if (node >= NN) return;
    int f = threadIdx.x;
    float dv = g_dinv[node];
    float4 hv = __ldg(&h[node * FQ + f]);
    float s = dv * dv;
    float4 acc = make_float4(s * hv.x, s * hv.y, s * hv.z, s * hv.w);
    int e = g_rowptr[node], end = g_rowptr[node + 1];
    for (; e + 3 < end; e += 4) {
        float w0 = g_val[e],     w1 = g_val[e + 1];
        float w2 = g_val[e + 2], w3 = g_val[e + 3];
        int c0 = g_col[e],     c1 = g_col[e + 1];
        int c2 = g_col[e + 2], c3 = g_col[e + 3];
        float4 n0 = __ldg(&h[c0 * FQ + f]);
        float4 n1 = __ldg(&h[c1 * FQ + f]);
        float4 n2 = __ldg(&h[c2 * FQ + f]);
        float4 n3 = __ldg(&h[c3 * FQ + f]);
        acc.x += w0 * n0.x + w1 * n1.x + w2 * n2.x + w3 * n3.x;
        acc.y += w0 * n0.y + w1 * n1.y + w2 * n2.y + w3 * n3.y;
        acc.z += w0 * n0.z + w1 * n1.z + w2 * n2.z + w3 * n3.z;
        acc.w += w0 * n0.w + w1 * n1.w + w2 * n2.w + w3 * n3.w;
    }
    for (; e < end; e++) {
        float w0 = g_val[e];
        float4 n0 = __ldg(&h[g_col[e] * FQ + f]);
        acc.x += w0 * n0.x; acc.y += w0 * n0.y;
        acc.z += w0 * n0.z; acc.w += w0 * n0.w;
    }
    out[node * FQ + f] = acc;
}

// ---------------- tf32 tensor-core GEMM: out = relu(in @ W + b) -------------
template <int K, int NTOT>
__global__ __launch_bounds__(256) void mma_tf32_kernel(
    const float* __restrict__ in, const float* __restrict__ Wt,
    const float* __restrict__ bias, float* __restrict__ out)
{
    constexpr int AS = K + 4;
    constexpr int NS = 128;
    constexpr int KQ = K / 4;
    extern __shared__ float smem[];
    float* sA = smem;
    float* sB = smem + 128 * AS;
    int tid = threadIdx.x;
    int node0 = blockIdx.x * 128;
    int n0 = blockIdx.y * NS;

    for (int i = tid; i < 128 * KQ; i += 256) {
        int r = i / KQ, kq = i - r * KQ;
        int nd = node0 + r;
        float4 v = make_float4(0.f, 0.f, 0.f, 0.f);
        if (nd < NN) v = __ldg((const float4*)in + (size_t)nd * KQ + kq);
        float* dst = sA + r * AS + kq * 4;
        dst[0] = __uint_as_float(f2tf32(v.x));
        dst[1] = __uint_as_float(f2tf32(v.y));
        dst[2] = __uint_as_float(f2tf32(v.z));
        dst[3] = __uint_as_float(f2tf32(v.w));
    }
    for (int i = tid; i < NS * KQ; i += 256) {
        int r = i / KQ, kq = i - r * KQ;
        float4 v = __ldg((const float4*)Wt + (size_t)(n0 + r) * KQ + kq);
        *(float4*)(sB + r * AS + kq * 4) = v;
    }
    __syncthreads();

    int warp = tid >> 5, lane = tid & 31;
    int g = lane >> 2, tg = lane & 3;
    int mrow = warp * 16;

    uint32_t a[K / 8][4];
    #pragma unroll
    for (int kk = 0; kk < K / 8; kk++) {
        const float* p0 = sA + (mrow + g) * AS + kk * 8 + tg;
        const float* p1 = sA + (mrow + g + 8) * AS + kk * 8 + tg;
        a[kk][0] = __float_as_uint(p0[0]);
        a[kk][1] = __float_as_uint(p1[0]);
        a[kk][2] = __float_as_uint(p0[4]);
        a[kk][3] = __float_as_uint(p1[4]);
    }

    int row0 = node0 + mrow + g;
    int row1 = row0 + 8;
    #pragma unroll 2
    for (int ng = 0; ng < NS / 8; ng++) {
        float d0 = 0.f, d1 = 0.f, d2 = 0.f, d3 = 0.f;
        const float* bp = sB + (ng * 8 + g) * AS + tg;
        #pragma unroll
        for (int kk = 0; kk < K / 8; kk++) {
            uint32_t b0 = __float_as_uint(bp[kk * 8]);
            uint32_t b1 = __float_as_uint(bp[kk * 8 + 4]);
            asm volatile(
                "mma.sync.aligned.m16n8k8.row.col.f32.tf32.tf32.f32 "
                "{%0,%1,%2,%3}, {%4,%5,%6,%7}, {%8,%9}, {%0,%1,%2,%3};"
                : "+f"(d0), "+f"(d1), "+f"(d2), "+f"(d3)
                : "r"(a[kk][0]), "r"(a[kk][1]), "r"(a[kk][2]), "r"(a[kk][3]),
                  "r"(b0), "r"(b1));
        }
        int col = n0 + ng * 8 + 2 * tg;
        float2 bs = __ldg((const float2*)&bias[col]);
        if (row0 < NN) {
            float2 o;
            o.x = fmaxf(d0 + bs.x, 0.f);
            o.y = fmaxf(d1 + bs.y, 0.f);
            *(float2*)(out + (size_t)row0 * NTOT + col) = o;
        }
        if (row1 < NN) {
            float2 o;
            o.x = fmaxf(d2 + bs.x, 0.f);
            o.y = fmaxf(d3 + bs.y, 0.f);
            *(float2*)(out + (size_t)row1 * NTOT + col) = o;
        }
    }
}

// ---------------- dense FFMA (layers 1-2) -----------------------------------
template <int K, int F, int TN>
__global__ __launch_bounds__(256) void gemm_relu_kernel(
    const float* __restrict__ in, const float* __restrict__ W,
    const float* __restrict__ bias, float* __restrict__ out)
{
    constexpr int TF = 4;
    constexpr int BX = F / TF;
    constexpr int BY = 256 / BX;
    constexpr int NT = TN * BY;
    constexpr int NTILES = (NN + NT - 1) / NT;
    extern __shared__ float fsm[];
    float* sW = fsm;
    float* sh = fsm + K * F;
    int tid = threadIdx.y * BX + threadIdx.x;

    const float4* Wv = (const float4*)W;
    float4* sWv = (float4*)sW;
    for (int i = tid; i < K * F / 4; i += 256) sWv[i] = Wv[i];

    int fq = threadIdx.x;
    float4 bv = ((const float4*)bias)[fq];

    for (int tile = blockIdx.x; tile < NTILES; tile += gridDim.x) {
        int node0 = tile * NT;
        __syncthreads();
        if constexpr (K % 4 == 0) {
            constexpr int KQ = K / 4;
            const float4* inv4 = (const float4*)in;
            float4* shv = (float4*)sh;
            for (int i = tid; i < NT * KQ; i += 256) {
                int j = i / KQ;
                int nd = node0 + j;
                shv[i] = (nd < NN) ? inv4[nd * KQ + (i - j * KQ)]
                                   : make_float4(0.f, 0.f, 0.f, 0.f);
            }
        } else {
            for (int i = tid; i < NT * K; i += 256) {
                int j = i / K, k = i - j * K;
                int nd = node0 + j;
                sh[i] = (nd < NN) ? in[nd * K + k] : 0.f;
            }
        }
        __syncthreads();

        float acc[TN][4];
        #pragma unroll
        for (int j = 0; j < TN; j++) {
            acc[j][0] = bv.x; acc[j][1] = bv.y; acc[j][2] = bv.z; acc[j][3] = bv.w;
        }
        const float* shb = sh + threadIdx.y * TN * K;
        #pragma unroll 4
        for (int k = 0; k < K; k++) {
            float4 w = ((const float4*)sW)[k * BX + fq];
            #pragma unroll
            for (int j = 0; j < TN; j++) {
                float hv = shb[j * K + k];
                acc[j][0] += w.x * hv;
                acc[j][1] += w.y * hv;
                acc[j][2] += w.z * hv;
                acc[j][3] += w.w * hv;
            }
        }
        #pragma unroll
        for (int j = 0; j < TN; j++) {
            int node = node0 + threadIdx.y * TN + j;
            if (node < NN) {
                float4 o;
                o.x = fmaxf(acc[j][0], 0.f);
                o.y = fmaxf(acc[j][1], 0.f);
                o.z = fmaxf(acc[j][2], 0.f);
                o.w = fmaxf(acc[j][3], 0.f);
                ((float4*)out)[node * BX + fq] = o;
            }
        }
    }
}

// ---------------- mean-pool + head ------------------------------------------
__global__ void pool_kernel(const float* __restrict__ h, const int* __restrict__ batch) {
    const int CH = 64;
    int f = threadIdx.x;
    int n0 = blockIdx.x * CH;
    float acc = 0.f;
    int curg = -1;
    for (int i = 0; i < CH; i++) {
        int nd = n0 + i;
        if (nd >= NN) break;
        int g = batch[nd];
        if (g != curg) {
            if (curg >= 0) atomicAdd(&g_pool[curg * 256 + f], acc);
            acc = 0.f; curg = g;
        }
        acc += h[nd * 256 + f];
    }
    if (curg >= 0) atomicAdd(&g_pool[curg * 256 + f], acc);
}

__global__ void head_kernel(const float* __restrict__ fcW, const float* __restrict__ fcb,
                            float* __restrict__ out) {
    __shared__ float slog[NG * NC];
    int tid = threadIdx.x;
    if (tid < NG * NC) {
        int g = tid / NC, c = tid % NC;
        float inv = 1.f / fmaxf(g_gcnt[g], 1.f);
        float a = fcb[c];
        for (int k = 0; k < 256; k++)
            a += g_pool[g * 256 + k] * inv * fcW[k * NC + c];
        slog[tid] = a;
    }
    __syncthreads();
    if (tid < NG * NC) {
        int g = tid / NC;
        float m = -1e30f;
        for (int i = 0; i < NC; i++) m = fmaxf(m, slog[g * NC + i]);
        float s = 0.f;
        for (int i = 0; i < NC; i++) s += expf(slog[g * NC + i] - m);
        out[tid] = slog[tid] - m - logf(s);
    }
}

// ---------------- launch -----------------------------------------------------
extern "C" void kernel_launch(void* const* d_in, const int* in_sizes, int n_in,
                              void* d_out, int out_size) {
    const float* x   = (const float*)d_in[0];
    const int*   ei  = (const int*)d_in[1];
    const int*   bat = (const int*)d_in[2];
    const float* W1 = (const float*)d_in[3];
    const float* b1 = (const float*)d_in[4];
    const float* W2 = (const float*)d_in[5];
    const float* b2 = (const float*)d_in[6];
    const float* W3 = (const float*)d_in[7];
    const float* b3 = (const float*)d_in[8];
    const float* W4 = (const float*)d_in[9];
    const float* b4 = (const float*)d_in[10];
    const float* fcW = (const float*)d_in[11];
    const float* fcb = (const float*)d_in[12];
    float* out = (float*)d_out;

    float *bufA, *bufB, *bufT, *Wt3, *Wt4;
    cudaGetSymbolAddress((void**)&bufA, g_bufA);
    cudaGetSymbolAddress((void**)&bufB, g_bufB);
    cudaGetSymbolAddress((void**)&bufT, g_bufT);
    cudaGetSymbolAddress((void**)&Wt3, g_Wt3);
    cudaGetSymbolAddress((void**)&Wt4, g_Wt4);

    const int smL3 = (128 * (64 + 4) + 128 * (64 + 4)) * 4;     // 69632
    const int smL4 = (128 * (128 + 4) + 128 * (128 + 4)) * 4;   // 135168
    cudaFuncSetAttribute(mma_tf32_kernel<64, 128>,
                         cudaFuncAttributeMaxDynamicSharedMemorySize, smL3);
    cudaFuncSetAttribute(mma_tf32_kernel<128, 256>,
                         cudaFuncAttributeMaxDynamicSharedMemorySize, smL4);

    const int EB = (NE + 255) / 256;
    const int NB = (NN + 255) / 256;

    init_kernel<<<NB, 256>>>(W3, W4);
    count_kernel<<<EB, 256>>>(ei);
    chunkred_kernel<<<NCHUNK, 256>>>();
    scan2_kernel<<<NCHUNK, 1024>>>();
    fillg_kernel<<<EB, 256>>>(ei, bat);

    // layer 1: agg(x)[5] -> @W1 -> relu -> bufA[32]
    {
        dim3 blk(5, 51);
        agg_kernel<5><<<(NN + 50) / 51, blk>>>(x, bufT);
        int smem = (5 * 32 + 128 * 5) * 4;
        gemm_relu_kernel<5, 32, 4><<<391, dim3(8, 32), smem>>>(bufT, W1, b1, bufA);
    }
    // layer 2: agg(bufA)[32] -> @W2 -> relu -> bufB[64]
    {
        dim3 blk(8, 32);
        agg4_kernel<32><<<(NN + 31) / 32, blk>>>((const float4*)bufA, (float4*)bufT);
        int smem = (32 * 64 + 64 * 32) * 4;
        gemm_relu_kernel<32, 64, 4><<<592, dim3(16, 16), smem>>>(bufT, W2, b2, bufB);
    }
    // layer 3: agg(bufB)[64] -> tf32 mma -> bufA[128]
    {
        dim3 blk(16, 16);
        agg4_kernel<64><<<(NN + 15) / 16, blk>>>((const float4*)bufB, (float4*)bufT);
        mma_tf32_kernel<64, 128><<<dim3(391, 1), 256, smL3>>>(bufT, Wt3, b3, bufA);
    }
    // layer 4: agg(bufA)[128] -> tf32 mma -> bufB[256]
    {
        dim3 blk(32, 8);
        agg4_kernel<128><<<(NN + 7) / 8, blk>>>((const float4*)bufA, (float4*)bufT);
        mma_tf32_kernel<128, 256><<<dim3(391, 2), 256, smL4>>>(bufT, Wt4, b4, bufB);
    }

    // mean pool + head
    pool_kernel<<<(NN + 63) / 64, 256>>>(bufB, bat);
    head_kernel<<<1, 640>>>(fcW, fcb, out);

    (void)in_sizes; (void)n_in; (void)out_size;
}

// round 8
// speedup vs baseline: 1.3410x; 1.1480x over previous
#include <cuda_runtime.h>
#include <cuda_bf16.h>
#include <math.h>
#include <stdint.h>

#define NN 50000
#define NE 800000
#define NG 64
#define NC 10
#define CHUNK 1024
#define NCHUNK ((NN + CHUNK - 1) / CHUNK)   // 49

__device__ __forceinline__ uint32_t f2tf32(float x) {
    uint32_t u;
    asm("cvt.rna.tf32.f32 %0, %1;" : "=r"(u) : "f"(x));
    return u;
}
__device__ __forceinline__ uint32_t pack_bf2(float a, float b) {
    __nv_bfloat162 p = __floats2bfloat162_rn(a, b);
    return *(uint32_t*)&p;
}
__device__ __forceinline__ float2 unpack_bf2(uint32_t u) {
    return __bfloat1622float2(*(__nv_bfloat162*)&u);
}

// ---------------- scratch (static device globals; no runtime alloc) --------
__device__ __align__(16) float g_dinv[NN];
__device__ int   g_cnt[NN];
__device__ int   g_rowptr[NN + 1];
__device__ int   g_cursor[NN];
__device__ int   g_col[NE];
__device__ float g_val[NE];
__device__ int   g_chunksum[NCHUNK];
__device__ __align__(16) float g_bufB[NN * 256];
__device__ __align__(16) float g_bufT[NN * 8];
__device__ __align__(16) __nv_bfloat16 g_b16A[NN * 128];
__device__ __align__(16) __nv_bfloat16 g_b16B[NN * 128];
__device__ __align__(16) float g_Wt3[128 * 64];    // W3^T, tf32-rounded
__device__ __align__(16) float g_Wt4[256 * 128];   // W4^T, tf32-rounded
__device__ float g_pool[NG * 256];
__device__ float g_gcnt[NG];

// ---------------- init: zero + weight transpose/round -----------------------
__global__ void init_kernel(const float* __restrict__ W3, const float* __restrict__ W4) {
    int i = blockIdx.x * blockDim.x + threadIdx.x;
    if (i < NN) g_cnt[i] = 0;
    if (i < NG * 256) g_pool[i] = 0.f;
    if (i < NG) g_gcnt[i] = 0.f;
    if (i < 128 * 64) {
        int n = i >> 6, k = i & 63;
        g_Wt3[i] = __uint_as_float(f2tf32(W3[k * 128 + n]));
    }
    if (i < 256 * 128) {
        int n = i >> 7, k = i & 127;
        g_Wt4[i] = __uint_as_float(f2tf32(W4[k * 256 + n]));
    }
}

__global__ void count_kernel(const int* __restrict__ ei) {
    int e = blockIdx.x * blockDim.x + threadIdx.x;
    if (e < NE) atomicAdd(&g_cnt[ei[NE + e]], 1);
}

__global__ void chunkred_kernel() {
    int c = blockIdx.x, tid = threadIdx.x;
    int base = c * CHUNK;
    int s = 0;
    #pragma unroll
    for (int k = 0; k < CHUNK / 256; k++) {
        int idx = base + tid + k * 256;
        if (idx < NN) {
            int v = g_cnt[idx];
            s += v;
            g_dinv[idx] = rsqrtf((float)(v + 1));
        }
    }
    for (int off = 16; off; off >>= 1) s += __shfl_down_sync(~0u, s, off);
    __shared__ int sm[8];
    if ((tid & 31) == 0) sm[tid >> 5] = s;
    __syncthreads();
    if (tid < 8) {
        int t = sm[tid];
        for (int off = 4; off; off >>= 1) t += __shfl_down_sync(0xff, t, off);
        if (tid == 0) g_chunksum[c] = t;
    }
}

// per-chunk scan; each block derives its own base from the 49 chunk sums
__global__ void scan2_kernel() {
    __shared__ int warpsum[32];
    __shared__ int part[2];
    __shared__ int base_s;
    int c = blockIdx.x, tid = threadIdx.x;

    if (tid < 64) {
        int v = (tid < c && tid < NCHUNK) ? g_chunksum[tid] : 0;
        for (int off = 16; off; off >>= 1) v += __shfl_down_sync(~0u, v, off);
        if ((tid & 31) == 0) part[tid >> 5] = v;
    }
    __syncthreads();
    if (tid == 0) base_s = part[0] + part[1];
    __syncthreads();

    int i = c * CHUNK + tid;
    int v = (i < NN) ? g_cnt[i] : 0;
    int lane = tid & 31, w = tid >> 5;
    int incl = v;
    for (int off = 1; off < 32; off <<= 1) {
        int t = __shfl_up_sync(~0u, incl, off);
        if (lane >= off) incl += t;
    }
    if (lane == 31) warpsum[w] = incl;
    __syncthreads();
    if (w == 0) {
        int ws = warpsum[lane];
        for (int off = 1; off < 32; off <<= 1) {
            int t = __shfl_up_sync(~0u, ws, off);
            if (lane >= off) ws += t;
        }
        warpsum[lane] = ws;
    }
    __syncthreads();
    int excl = incl - v + (w > 0 ? warpsum[w - 1] : 0) + base_s;
    if (i < NN) { g_rowptr[i] = excl; g_cursor[i] = excl; }
    if (i == NN - 1) g_rowptr[NN] = excl + v;
}

__global__ void fillg_kernel(const int* __restrict__ ei, const int* __restrict__ bat) {
    int e = blockIdx.x * blockDim.x + threadIdx.x;
    if (e < NE) {
        int s = ei[e];
        int d = ei[NE + e];
        int pos = atomicAdd(&g_cursor[d], 1);
        g_col[pos] = s;
        g_val[pos] = g_dinv[s] * g_dinv[d];
    }
    if (e < NN) atomicAdd(&g_gcnt[bat[e]], 1.f);
}

// ---------------- aggregation ------------------------------------------------
// f32 scalar (layer 1 only, F=5)
template <int F>
__global__ void agg_kernel(const float* __restrict__ h, float* __restrict__ out) {
    int node = blockIdx.x * blockDim.y + threadIdx.y;
    if (node >= NN) return;
    int f = threadIdx.x;
    float dv = g_dinv[node];
    float acc = dv * dv * __ldg(&h[node * F + f]);
    int e = g_rowptr[node], end = g_rowptr[node + 1];
    for (; e < end; e++) acc += g_val[e] * __ldg(&h[g_col[e] * F + f]);
    out[node * F + f] = acc;
}

// bf16 in -> bf16 out, fp32 accumulate. threads.x = F/8 (one uint4 per thread)
template <int F>
__global__ void aggb_kernel(const uint4* __restrict__ h, uint4* __restrict__ out) {
    constexpr int FQ8 = F / 8;
    int node = blockIdx.x * blockDim.y + threadIdx.y;
    if (node >= NN) return;
    int f = threadIdx.x;
    float dv = g_dinv[node];
    float s = dv * dv;
    float acc[8];
    {
        uint4 v = __ldg(&h[(size_t)node * FQ8 + f]);
        const uint32_t* u = (const uint32_t*)&v;
        #pragma unroll
        for (int j = 0; j < 4; j++) {
            float2 fv = unpack_bf2(u[j]);
            acc[2 * j] = s * fv.x; acc[2 * j + 1] = s * fv.y;
        }
    }
    int e = g_rowptr[node], end = g_rowptr[node + 1];
    for (; e + 3 < end; e += 4) {
        float w0 = g_val[e],     w1 = g_val[e + 1];
        float w2 = g_val[e + 2], w3 = g_val[e + 3];
        int c0 = g_col[e],     c1 = g_col[e + 1];
        int c2 = g_col[e + 2], c3 = g_col[e + 3];
        uint4 v0 = __ldg(&h[(size_t)c0 * FQ8 + f]);
        uint4 v1 = __ldg(&h[(size_t)c1 * FQ8 + f]);
        uint4 v2 = __ldg(&h[(size_t)c2 * FQ8 + f]);
        uint4 v3 = __ldg(&h[(size_t)c3 * FQ8 + f]);
        const uint32_t* u0 = (const uint32_t*)&v0;
        const uint32_t* u1 = (const uint32_t*)&v1;
        const uint32_t* u2 = (const uint32_t*)&v2;
        const uint32_t* u3 = (const uint32_t*)&v3;
        #pragma unroll
        for (int j = 0; j < 4; j++) {
            float2 f0 = unpack_bf2(u0[j]);
            float2 f1 = unpack_bf2(u1[j]);
            float2 f2 = unpack_bf2(u2[j]);
            float2 f3 = unpack_bf2(u3[j]);
            acc[2 * j]     += w0 * f0.x + w1 * f1.x + w2 * f2.x + w3 * f3.x;
            acc[2 * j + 1] += w0 * f0.y + w1 * f1.y + w2 * f2.y + w3 * f3.y;
        }
    }
    for (; e < end; e++) {
        float w0 = g_val[e];
        uint4 v0 = __ldg(&h[(size_t)g_col[e] * FQ8 + f]);
        const uint32_t* u0 = (const uint32_t*)&v0;
        #pragma unroll
        for (int j = 0; j < 4; j++) {
            float2 f0 = unpack_bf2(u0[j]);
            acc[2 * j] += w0 * f0.x; acc[2 * j + 1] += w0 * f0.y;
        }
    }
    uint32_t pk[4];
    #pragma unroll
    for (int j = 0; j < 4; j++) pk[j] = pack_bf2(acc[2 * j], acc[2 * j + 1]);
    out[(size_t)node * FQ8 + f] = *(uint4*)pk;
}

// ---------------- tf32 tensor-core GEMM: out = relu(A @ W^T + b) ------------
// A: [NN][K] bf16, Wt: [NTOT][K] tf32-in-f32, out bf16 (OUTB=1) or f32.
template <int K, int NTOT, int OUTB>
__global__ __launch_bounds__(256) void mma_tf32_kernel(
    const __nv_bfloat16* __restrict__ A, const float* __restrict__ Wt,
    const float* __restrict__ bias, void* __restrict__ outp)
{
    constexpr int AS = K + 4;
    constexpr int NS = 128;
    constexpr int KQ = K / 4;
    constexpr int KQ8 = K / 8;
    extern __shared__ float smem[];
    float* sA = smem;
    float* sB = smem + 128 * AS;
    int tid = threadIdx.x;
    int node0 = blockIdx.x * 128;
    int n0 = blockIdx.y * NS;

    // stage A: bf16 -> f32 (bf16 mantissa fits tf32, no extra rounding needed)
    const uint4* Ab = (const uint4*)A;
    for (int i = tid; i < 128 * KQ8; i += 256) {
        int r = i / KQ8, c = i - r * KQ8;
        int nd = node0 + r;
        uint4 v = make_uint4(0, 0, 0, 0);
        if (nd < NN) v = __ldg(&Ab[(size_t)nd * KQ8 + c]);
        const uint32_t* u = (const uint32_t*)&v;
        float* dst = sA + r * AS + c * 8;
        #pragma unroll
        for (int j = 0; j < 4; j++) {
            float2 fv = unpack_bf2(u[j]);
            dst[2 * j] = fv.x; dst[2 * j + 1] = fv.y;
        }
    }
    for (int i = tid; i < NS * KQ; i += 256) {
        int r = i / KQ, kq = i - r * KQ;
        float4 v = __ldg((const float4*)Wt + (size_t)(n0 + r) * KQ + kq);
        *(float4*)(sB + r * AS + kq * 4) = v;
    }
    __syncthreads();

    int warp = tid >> 5, lane = tid & 31;
    int g = lane >> 2, tg = lane & 3;
    int mrow = warp * 16;

    uint32_t a[K / 8][4];
    #pragma unroll
    for (int kk = 0; kk < K / 8; kk++) {
        const float* p0 = sA + (mrow + g) * AS + kk * 8 + tg;
        const float* p1 = sA + (mrow + g + 8) * AS + kk * 8 + tg;
        a[kk][0] = __float_as_uint(p0[0]);
        a[kk][1] = __float_as_uint(p1[0]);
        a[kk][2] = __float_as_uint(p0[4]);
        a[kk][3] = __float_as_uint(p1[4]);
    }

    int row0 = node0 + mrow + g;
    int row1 = row0 + 8;
    #pragma unroll 2
    for (int ng = 0; ng < NS / 8; ng++) {
        float d0 = 0.f, d1 = 0.f, d2 = 0.f, d3 = 0.f;
        const float* bp = sB + (ng * 8 + g) * AS + tg;
        #pragma unroll
        for (int kk = 0; kk < K / 8; kk++) {
            uint32_t b0 = __float_as_uint(bp[kk * 8]);
            uint32_t b1 = __float_as_uint(bp[kk * 8 + 4]);
            asm volatile(
                "mma.sync.aligned.m16n8k8.row.col.f32.tf32.tf32.f32 "
                "{%0,%1,%2,%3}, {%4,%5,%6,%7}, {%8,%9}, {%0,%1,%2,%3};"
                : "+f"(d0), "+f"(d1), "+f"(d2), "+f"(d3)
                : "r"(a[kk][0]), "r"(a[kk][1]), "r"(a[kk][2]), "r"(a[kk][3]),
                  "r"(b0), "r"(b1));
        }
        int col = n0 + ng * 8 + 2 * tg;
        float2 bs = __ldg((const float2*)&bias[col]);
        float o0x = fmaxf(d0 + bs.x, 0.f), o0y = fmaxf(d1 + bs.y, 0.f);
        float o1x = fmaxf(d2 + bs.x, 0.f), o1y = fmaxf(d3 + bs.y, 0.f);
        if constexpr (OUTB) {
            __nv_bfloat16* ob = (__nv_bfloat16*)outp;
            if (row0 < NN) *(uint32_t*)(ob + (size_t)row0 * NTOT + col) = pack_bf2(o0x, o0y);
            if (row1 < NN) *(uint32_t*)(ob + (size_t)row1 * NTOT + col) = pack_bf2(o1x, o1y);
        } else {
            float* of = (float*)outp;
            if (row0 < NN) *(float2*)(of + (size_t)row0 * NTOT + col) = make_float2(o0x, o0y);
            if (row1 < NN) *(float2*)(of + (size_t)row1 * NTOT + col) = make_float2(o1x, o1y);
        }
    }
}

// ---------------- dense FFMA (layers 1-2): out = relu(in @ W + b) -----------
// INB: input bf16; OUTB: output bf16.
template <int K, int F, int TN, int INB, int OUTB>
__global__ __launch_bounds__(256) void gemm_relu_kernel(
    const void* __restrict__ inp, const float* __restrict__ W,
    const float* __restrict__ bias, void* __restrict__ outp)
{
    constexpr int TF = 4;
    constexpr int BX = F / TF;
    constexpr int BY = 256 / BX;
    constexpr int NT = TN * BY;
    constexpr int NTILES = (NN + NT - 1) / NT;
    extern __shared__ float fsm[];
    float* sW = fsm;
    float* sh = fsm + K * F;
    int tid = threadIdx.y * BX + threadIdx.x;

    const float4* Wv = (const float4*)W;
    float4* sWv = (float4*)sW;
    for (int i = tid; i < K * F / 4; i += 256) sWv[i] = Wv[i];

    int fq = threadIdx.x;
    float4 bv = ((const float4*)bias)[fq];

    for (int tile = blockIdx.x; tile < NTILES; tile += gridDim.x) {
        int node0 = tile * NT;
        __syncthreads();
        if constexpr (INB) {
            constexpr int KQ = K / 4;
            const uint2* inb = (const uint2*)inp;
            for (int i = tid; i < NT * KQ; i += 256) {
                int j = i / KQ, kq = i - j * KQ;
                int nd = node0 + j;
                uint2 v = make_uint2(0, 0);
                if (nd < NN) v = __ldg(&inb[(size_t)nd * KQ + kq]);
                float2 f0 = unpack_bf2(v.x), f1 = unpack_bf2(v.y);
                float* d = sh + j * K + kq * 4;
                d[0] = f0.x; d[1] = f0.y; d[2] = f1.x; d[3] = f1.y;
            }
        } else {
            const float* in = (const float*)inp;
            for (int i = tid; i < NT * K; i += 256) {
                int j = i / K, k = i - j * K;
                int nd = node0 + j;
                sh[i] = (nd < NN) ? in[(size_t)nd * K + k] : 0.f;
            }
        }
        __syncthreads();

        float acc[TN][4];
        #pragma unroll
        for (int j = 0; j < TN; j++) {
            acc[j][0] = bv.x; acc[j][1] = bv.y; acc[j][2] = bv.z; acc[j][3] = bv.w;
        }
        const float* shb = sh + threadIdx.y * TN * K;
        #pragma unroll 4
        for (int k = 0; k < K; k++) {
            float4 w = ((const float4*)sW)[k * BX + fq];
            #pragma unroll
            for (int j = 0; j < TN; j++) {
                float hv = shb[j * K + k];
                acc[j][0] += w.x * hv;
                acc[j][1] += w.y * hv;
                acc[j][2] += w.z * hv;
                acc[j][3] += w.w * hv;
            }
        }
        #pragma unroll
        for (int j = 0; j < TN; j++) {
            int node = node0 + threadIdx.y * TN + j;
            if (node < NN) {
                float ox = fmaxf(acc[j][0], 0.f);
                float oy = fmaxf(acc[j][1], 0.f);
                float oz = fmaxf(acc[j][2], 0.f);
                float ow = fmaxf(acc[j][3], 0.f);
                if constexpr (OUTB) {
                    uint2 pk;
                    pk.x = pack_bf2(ox, oy);
                    pk.y = pack_bf2(oz, ow);
                    ((uint2*)((__nv_bfloat16*)outp + (size_t)node * F))[fq] = pk;
                } else {
                    ((float4*)outp)[(size_t)node * BX + fq] = make_float4(ox, oy, oz, ow);
                }
            }
        }
    }
}

// ---------------- mean-pool + head ------------------------------------------
__global__ void pool_kernel(const float* __restrict__ h, const int* __restrict__ batch) {
    const int CH = 64;
    int f = threadIdx.x;
    int n0 = blockIdx.x * CH;
    float acc = 0.f;
    int curg = -1;
    for (int i = 0; i < CH; i++) {
        int nd = n0 + i;
        if (nd >= NN) break;
        int g = batch[nd];
        if (g != curg) {
            if (curg >= 0) atomicAdd(&g_pool[curg * 256 + f], acc);
            acc = 0.f; curg = g;
        }
        acc += h[(size_t)nd * 256 + f];
    }
    if (curg >= 0) atomicAdd(&g_pool[curg * 256 + f], acc);
}

__global__ void head_kernel(const float* __restrict__ fcW, const float* __restrict__ fcb,
                            float* __restrict__ out) {
    __shared__ float slog[NG * NC];
    int tid = threadIdx.x;
    if (tid < NG * NC) {
        int g = tid / NC, c = tid % NC;
        float inv = 1.f / fmaxf(g_gcnt[g], 1.f);
        float a = fcb[c];
        for (int k = 0; k < 256; k++)
            a += g_pool[g * 256 + k] * inv * fcW[k * NC + c];
        slog[tid] = a;
    }
    __syncthreads();
    if (tid < NG * NC) {
        int g = tid / NC;
        float m = -1e30f;
        for (int i = 0; i < NC; i++) m = fmaxf(m, slog[g * NC + i]);
        float s = 0.f;
        for (int i = 0; i < NC; i++) s += expf(slog[g * NC + i] - m);
        out[tid] = slog[tid] - m - logf(s);
    }
}

// ---------------- launch -----------------------------------------------------
extern "C" void kernel_launch(void* const* d_in, const int* in_sizes, int n_in,
                              void* d_out, int out_size) {
    const float* x   = (const float*)d_in[0];
    const int*   ei  = (const int*)d_in[1];
    const int*   bat = (const int*)d_in[2];
    const float* W1 = (const float*)d_in[3];
    const float* b1 = (const float*)d_in[4];
    const float* W2 = (const float*)d_in[5];
    const float* b2 = (const float*)d_in[6];
    const float* W3 = (const float*)d_in[7];
    const float* b3 = (const float*)d_in[8];
    const float* W4 = (const float*)d_in[9];
    const float* b4 = (const float*)d_in[10];
    const float* fcW = (const float*)d_in[11];
    const float* fcb = (const float*)d_in[12];
    float* out = (float*)d_out;

    float *bufB, *bufT, *Wt3, *Wt4;
    __nv_bfloat16 *bA, *bB;
    cudaGetSymbolAddress((void**)&bufB, g_bufB);
    cudaGetSymbolAddress((void**)&bufT, g_bufT);
    cudaGetSymbolAddress((void**)&bA, g_b16A);
    cudaGetSymbolAddress((void**)&bB, g_b16B);
    cudaGetSymbolAddress((void**)&Wt3, g_Wt3);
    cudaGetSymbolAddress((void**)&Wt4, g_Wt4);

    const int smL3 = (128 * (64 + 4) + 128 * (64 + 4)) * 4;     // 69632
    const int smL4 = (128 * (128 + 4) + 128 * (128 + 4)) * 4;   // 135168
    cudaFuncSetAttribute(mma_tf32_kernel<64, 128, 1>,
                         cudaFuncAttributeMaxDynamicSharedMemorySize, smL3);
    cudaFuncSetAttribute(mma_tf32_kernel<128, 256, 0>,
                         cudaFuncAttributeMaxDynamicSharedMemorySize, smL4);

    const int EB = (NE + 255) / 256;
    const int NB = (NN + 255) / 256;

    init_kernel<<<NB, 256>>>(W3, W4);
    count_kernel<<<EB, 256>>>(ei);
    chunkred_kernel<<<NCHUNK, 256>>>();
    scan2_kernel<<<NCHUNK, 1024>>>();
    fillg_kernel<<<EB, 256>>>(ei, bat);

    // layer 1: agg(x f32)[5] -> FFMA gemm -> bA bf16 [NN][32]
    {
        dim3 blk(5, 51);
        agg_kernel<5><<<(NN + 50) / 51, blk>>>(x, bufT);
        int smem = (5 * 32 + 128 * 5) * 4;
        gemm_relu_kernel<5, 32, 4, 0, 1><<<391, dim3(8, 32), smem>>>(bufT, W1, b1, bA);
    }
    // layer 2: aggb(bA)[32] -> bB; FFMA gemm (bf16 in) -> bA bf16 [NN][64]
    {
        dim3 blk(4, 64);
        aggb_kernel<32><<<(NN + 63) / 64, blk>>>((const uint4*)bA, (uint4*)bB);
        int smem = (32 * 64 + 64 * 32) * 4;
        gemm_relu_kernel<32, 64, 4, 1, 1><<<592, dim3(16, 16), smem>>>(bB, W2, b2, bA);
    }
    // layer 3: aggb(bA)[64] -> bB; tf32 mma -> bA bf16 [NN][128]
    {
        dim3 blk(8, 32);
        aggb_kernel<64><<<(NN + 31) / 32, blk>>>((const uint4*)bA, (uint4*)bB);
        mma_tf32_kernel<64, 128, 1><<<dim3(391, 1), 256, smL3>>>(bB, Wt3, b3, bA);
    }
    // layer 4: aggb(bA)[128] -> bB; tf32 mma -> bufB f32 [NN][256]
    {
        dim3 blk(16, 16);
        aggb_kernel<128><<<(NN + 15) / 16, blk>>>((const uint4*)bA, (uint4*)bB);
        mma_tf32_kernel<128, 256, 0><<<dim3(391, 2), 256, smL4>>>(bB, Wt4, b4, bufB);
    }

    // mean pool + head
    pool_kernel<<<(NN + 63) / 64, 256>>>(bufB, bat);
    head_kernel<<<1, 640>>>(fcW, fcb, out);

    (void)in_sizes; (void)n_in; (void)out_size;
}